// round 11
// baseline (speedup 1.0000x reference)
#include <cuda_runtime.h>
#include <cstdint>
#include <cstddef>

// ---------------------------------------------------------------------------
// Layer-sequential 2-layer GRU, L2-streamed weights with 4-batch reuse.
//   K1: 32 CTAs x 832 thr, 4 batches/CTA. Thread r<600 streams W_hh0 row r
//       from L2 (LDG.128) each step, FMA2s it against 4 batches' h0 (smem
//       broadcast). Dots -> smem; cell threads (j,b) update h0, STG to g_h0.
//   K2: 512 CTAs (b x row-quarter): gx1 = W_ih1 . h0  tiled GEMM, weight
//       quarter-rows in 25 u64 regs, 8-step h tiles in smem.
//   K3: 32 CTAs: layer-1 recurrence streaming W_hh1 + gx1 ring from gmem,
//       FC outputs in aux warp.
// All weights are read repeatedly from a single L2-resident copy.
// ---------------------------------------------------------------------------

#define TSTEPS 1024
#define HDIM   200
#define NBATCH 128

typedef unsigned long long u64;

__device__ float g_h0[(size_t)NBATCH * TSTEPS * HDIM];    // 105 MB
__device__ float g_gx1[(size_t)NBATCH * TSTEPS * 600];    // 315 MB

#define FMA2(acc_, a_, b_) \
  asm("fma.rn.f32x2 %0, %1, %2, %0;" : "+l"(acc_) : "l"(a_), "l"(b_))
#define UNPK2(lo_, hi_, v_) \
  asm("mov.b64 {%0,%1}, %2;" : "=f"(lo_), "=f"(hi_) : "l"(v_))

__device__ __forceinline__ float sigmoid_f(float x) {
  return __fdividef(1.0f, 1.0f + __expf(-x));
}
__device__ __forceinline__ float tanh_f(float x) {
  float e = __expf(-2.0f * x);
  return __fdividef(2.0f, 1.0f + e) - 1.0f;
}

// ============================ K1: layer 0 ==================================
__global__ void __launch_bounds__(832, 1)
k1_layer0(const float* __restrict__ x,
          const float* __restrict__ W_ih0, const float* __restrict__ W_hh0,
          const float* __restrict__ b_ih0, const float* __restrict__ b_hh0)
{
  __shared__ __align__(16) float sh[2*4*HDIM];     // h0 ring [2][4][200]
  __shared__ __align__(16) float sdots[3*4*HDIM];  // dots [g][b][j]
  __shared__ float sI[2*4*8];                      // input ring [2][4][8]
  __shared__ float sW[600*8];                      // W_ih0
  __shared__ float sB[800];

  const int tid = threadIdx.x;
  const int b0 = blockIdx.x * 4;

  for (int f = tid; f < 4800; f += 832) sW[f] = W_ih0[f];
  for (int f = tid; f < 200; f += 832) {
    sB[f]       = b_ih0[f]       + b_hh0[f];
    sB[200 + f] = b_ih0[200 + f] + b_hh0[200 + f];
    sB[400 + f] = b_ih0[400 + f];
    sB[600 + f] = b_hh0[400 + f];
  }
  for (int f = tid; f < 2*4*HDIM; f += 832) sh[f] = 0.f;

  float4 xnext = make_float4(0.f, 0.f, 0.f, 0.f);
  if (tid >= 800 && tid < 804) {
    const int bb = tid - 800;
    const float* xr = x + (size_t)(b0 + bb) * TSTEPS * 8;
    float4 em = *(const float4*)(xr + 4);
    float* i0 = sI + bb*8;
    float* i1 = sI + 32 + bb*8;
    i0[0] = 1.f; i0[1] = 1.f; i0[2] = 1.f; i0[3] = 1.f;
    i0[4] = em.x; i0[5] = em.y; i0[6] = em.z; i0[7] = em.w;
    i1[4] = em.x; i1[5] = em.y; i1[6] = em.z; i1[7] = em.w;
    xnext = *(const float4*)(xr);     // tf for step 1
  }
  __syncthreads();

  const int r = tid;                  // weight row (tid < 600)
  const int gidx = r / 200, jr = r % 200;
  const ulonglong2* wrow = (const ulonglong2*)(W_hh0 + (size_t)r * HDIM);

  for (int t = 0; t < TSTEPS; t++) {
    const int p = t & 1, q = p ^ 1;

    if (tid < 600) {
      const float* hb = sh + p*800;
      u64 a0 = 0, a1 = 0, a2 = 0, a3 = 0;
      #pragma unroll 5
      for (int c = 0; c < 25; c++) {
        ulonglong2 W1 = wrow[2*c];        // w[8c..8c+3]
        ulonglong2 W2 = wrow[2*c + 1];    // w[8c+4..8c+7]
        {
          const ulonglong2* h8 = (const ulonglong2*)(hb + 0*HDIM + c*8);
          ulonglong2 Ha = h8[0], Hb = h8[1];
          FMA2(a0, W1.x, Ha.x); FMA2(a0, W1.y, Ha.y);
          FMA2(a0, W2.x, Hb.x); FMA2(a0, W2.y, Hb.y);
        }
        {
          const ulonglong2* h8 = (const ulonglong2*)(hb + 1*HDIM + c*8);
          ulonglong2 Ha = h8[0], Hb = h8[1];
          FMA2(a1, W1.x, Ha.x); FMA2(a1, W1.y, Ha.y);
          FMA2(a1, W2.x, Hb.x); FMA2(a1, W2.y, Hb.y);
        }
        {
          const ulonglong2* h8 = (const ulonglong2*)(hb + 2*HDIM + c*8);
          ulonglong2 Ha = h8[0], Hb = h8[1];
          FMA2(a2, W1.x, Ha.x); FMA2(a2, W1.y, Ha.y);
          FMA2(a2, W2.x, Hb.x); FMA2(a2, W2.y, Hb.y);
        }
        {
          const ulonglong2* h8 = (const ulonglong2*)(hb + 3*HDIM + c*8);
          ulonglong2 Ha = h8[0], Hb = h8[1];
          FMA2(a3, W1.x, Ha.x); FMA2(a3, W1.y, Ha.y);
          FMA2(a3, W2.x, Hb.x); FMA2(a3, W2.y, Hb.y);
        }
      }
      float lo, hi;
      float* dd = sdots + gidx*800 + jr;
      UNPK2(lo, hi, a0); dd[0]   = lo + hi;
      UNPK2(lo, hi, a1); dd[200] = lo + hi;
      UNPK2(lo, hi, a2); dd[400] = lo + hi;
      UNPK2(lo, hi, a3); dd[600] = lo + hi;
    } else if (tid >= 800 && tid < 804) {
      // stage tf for step t+1 into sI[q]; prefetch next
      float* ib = sI + q*32 + (tid - 800)*8;
      ib[0] = xnext.x; ib[1] = xnext.y; ib[2] = xnext.z; ib[3] = xnext.w;
      if (t + 1 < TSTEPS)
        xnext = *(const float4*)(x + ((size_t)(b0 + tid - 800) * TSTEPS + (t + 1)) * 8);
    }
    __syncthreads();

    if (tid < 800) {
      const int b = tid & 3, j = tid >> 2;
      float dr = sdots[        b*200 + j];
      float dz = sdots[ 800 + b*200 + j];
      float dn = sdots[1600 + b*200 + j];
      const float* ib = sI + p*32 + b*8;
      float xr = sB[j], xz = sB[200 + j], xn = sB[400 + j];
      #pragma unroll
      for (int c = 0; c < 8; c++) {
        float ic = ib[c];
        xr = fmaf(sW[        j*8  + c], ic, xr);
        xz = fmaf(sW[(200 + j)*8 + c], ic, xz);
        xn = fmaf(sW[(400 + j)*8 + c], ic, xn);
      }
      float rr = sigmoid_f(xr + dr);
      float zz = sigmoid_f(xz + dz);
      float nn = tanh_f(xn + rr * (dn + sB[600 + j]));
      float ho = sh[p*800 + b*200 + j];
      float hn = nn + zz * (ho - nn);
      sh[q*800 + b*200 + j] = hn;
      g_h0[((size_t)(b0 + b) * TSTEPS + t) * HDIM + j] = hn;
    }
    __syncthreads();
  }
}

// ============================ K2: gx1 GEMM =================================
__global__ void __launch_bounds__(608, 1)
k2_gx1(const float* __restrict__ W_ih1)
{
  __shared__ __align__(16) float ht[8 * HDIM];    // 8-step h tile

  const int tid = threadIdx.x;
  const int b  = blockIdx.x >> 2;
  const int rq = blockIdx.x & 3;

  const int row = tid >> 2, q4 = tid & 3;          // row<150 (tid<600)
  const int grow = rq*150 + row;
  const unsigned mask = (tid < 576) ? 0xffffffffu : 0x00ffffffu;

  u64 wreg[25];
  if (tid < 600) {
    const u64* src = (const u64*)(W_ih1 + (size_t)grow * HDIM + q4*50);
    #pragma unroll
    for (int c = 0; c < 25; c++) wreg[c] = src[c];
  }

  const float* hin = g_h0 + (size_t)b * TSTEPS * HDIM;
  float* gout = g_gx1 + (size_t)b * TSTEPS * 600;

  for (int tb = 0; tb < TSTEPS; tb += 8) {
    __syncthreads();
    // load 8x200 h tile (coalesced)
    if (tid < 400)
      ((float4*)ht)[tid] = ((const float4*)(hin + (size_t)tb * HDIM))[tid];
    __syncthreads();
    if (tid < 600) {
      #pragma unroll 2
      for (int tt = 0; tt < 8; tt++) {
        const u64* hq = (const u64*)(ht + tt*HDIM + q4*50);
        u64 acc = 0;
        #pragma unroll
        for (int c = 0; c < 25; c++) FMA2(acc, wreg[c], hq[c]);
        float lo, hi;
        UNPK2(lo, hi, acc);
        float d = lo + hi;
        d += __shfl_xor_sync(mask, d, 1);
        d += __shfl_xor_sync(mask, d, 2);
        if (q4 == 0) gout[(size_t)(tb + tt)*600 + grow] = d;
      }
    }
  }
}

// ============================ K3: layer 1 + FC =============================
__global__ void __launch_bounds__(832, 1)
k3_layer1(const float* __restrict__ W_hh1,
          const float* __restrict__ b_ih1, const float* __restrict__ b_hh1,
          const float* __restrict__ W_fc,  const float* __restrict__ b_fc,
          float* __restrict__ out)
{
  __shared__ __align__(16) float sh[2*4*HDIM];     // h1 ring
  __shared__ __align__(16) float sdots[3*4*HDIM];
  __shared__ float sB[800];
  __shared__ float sF[800];
  __shared__ float sbf[4];

  const int tid = threadIdx.x;
  const int b0 = blockIdx.x * 4;

  for (int f = tid; f < 800; f += 832) sF[f] = W_fc[f];
  for (int f = tid; f < 200; f += 832) {
    sB[f]       = b_ih1[f]       + b_hh1[f];
    sB[200 + f] = b_ih1[200 + f] + b_hh1[200 + f];
    sB[400 + f] = b_ih1[400 + f];
    sB[600 + f] = b_hh1[400 + f];
  }
  for (int f = tid; f < 2*4*HDIM; f += 832) sh[f] = 0.f;
  if (tid < 4) sbf[tid] = b_fc[tid];

  const int r = tid;
  const int gidx = r / 200, jr = r % 200;
  const ulonglong2* wrow = (const ulonglong2*)(W_hh1 + (size_t)r * HDIM);

  // gx1 prefetch ring (cell threads): u for even t, v for odd t
  const int cb = tid & 3, cj = tid >> 2;     // cell (j,b) for tid<800
  const float* gin = g_gx1 + (size_t)(b0 + cb) * TSTEPS * 600;
  float u0=0.f,u1=0.f,u2=0.f, v0=0.f,v1=0.f,v2=0.f;
  if (tid < 800) {
    u0 = gin[cj];        u1 = gin[200 + cj];  u2 = gin[400 + cj];
    v0 = gin[600 + cj];  v1 = gin[800 + cj];  v2 = gin[1000 + cj];
  }
  __syncthreads();

  for (int t = 0; t < TSTEPS; t++) {
    const int p = t & 1, q = p ^ 1;

    if (tid < 600) {
      const float* hb = sh + p*800;
      u64 a0 = 0, a1 = 0, a2 = 0, a3 = 0;
      #pragma unroll 5
      for (int c = 0; c < 25; c++) {
        ulonglong2 W1 = wrow[2*c];
        ulonglong2 W2 = wrow[2*c + 1];
        {
          const ulonglong2* h8 = (const ulonglong2*)(hb + 0*HDIM + c*8);
          ulonglong2 Ha = h8[0], Hb = h8[1];
          FMA2(a0, W1.x, Ha.x); FMA2(a0, W1.y, Ha.y);
          FMA2(a0, W2.x, Hb.x); FMA2(a0, W2.y, Hb.y);
        }
        {
          const ulonglong2* h8 = (const ulonglong2*)(hb + 1*HDIM + c*8);
          ulonglong2 Ha = h8[0], Hb = h8[1];
          FMA2(a1, W1.x, Ha.x); FMA2(a1, W1.y, Ha.y);
          FMA2(a1, W2.x, Hb.x); FMA2(a1, W2.y, Hb.y);
        }
        {
          const ulonglong2* h8 = (const ulonglong2*)(hb + 2*HDIM + c*8);
          ulonglong2 Ha = h8[0], Hb = h8[1];
          FMA2(a2, W1.x, Ha.x); FMA2(a2, W1.y, Ha.y);
          FMA2(a2, W2.x, Hb.x); FMA2(a2, W2.y, Hb.y);
        }
        {
          const ulonglong2* h8 = (const ulonglong2*)(hb + 3*HDIM + c*8);
          ulonglong2 Ha = h8[0], Hb = h8[1];
          FMA2(a3, W1.x, Ha.x); FMA2(a3, W1.y, Ha.y);
          FMA2(a3, W2.x, Hb.x); FMA2(a3, W2.y, Hb.y);
        }
      }
      float lo, hi;
      float* dd = sdots + gidx*800 + jr;
      UNPK2(lo, hi, a0); dd[0]   = lo + hi;
      UNPK2(lo, hi, a1); dd[200] = lo + hi;
      UNPK2(lo, hi, a2); dd[400] = lo + hi;
      UNPK2(lo, hi, a3); dd[600] = lo + hi;
    } else if (tid >= 800 && tid < 816 && t > 0) {
      // FC: out[t-1] for batch bb, output o, on h1_post(t-1) = sh[p]
      const int o = (tid - 800) & 3, bb = (tid - 800) >> 2;
      const float* wf = sF + o*HDIM;
      const float* hv = sh + p*800 + bb*HDIM;
      float s0 = 0.f, s1 = 0.f, s2 = 0.f, s3 = 0.f;
      #pragma unroll 10
      for (int k = 0; k < HDIM; k += 4) {
        float4 W = *(const float4*)(wf + k);
        float4 H = *(const float4*)(hv + k);
        s0 = fmaf(W.x, H.x, s0); s1 = fmaf(W.y, H.y, s1);
        s2 = fmaf(W.z, H.z, s2); s3 = fmaf(W.w, H.w, s3);
      }
      float v = tanh_f(s0 + s1 + s2 + s3 + sbf[o]);
      out[((size_t)(b0 + bb) * TSTEPS + (t - 1)) * 4 + o] = v;
    }
    __syncthreads();

    if (tid < 800) {
      float dr = sdots[        cb*200 + cj];
      float dz = sdots[ 800 + cb*200 + cj];
      float dn = sdots[1600 + cb*200 + cj];
      float gr = p ? v0 : u0;
      float gz = p ? v1 : u1;
      float gn = p ? v2 : u2;
      float rr = sigmoid_f(gr + dr + sB[cj]);
      float zz = sigmoid_f(gz + dz + sB[200 + cj]);
      float nn = tanh_f(gn + sB[400 + cj] + rr * (dn + sB[600 + cj]));
      float ho = sh[p*800 + cb*200 + cj];
      float hn = nn + zz * (ho - nn);
      sh[q*800 + cb*200 + cj] = hn;
      if (t + 2 < TSTEPS) {
        const float* gp = gin + (size_t)(t + 2) * 600;
        if (p) { v0 = gp[cj]; v1 = gp[200 + cj]; v2 = gp[400 + cj]; }
        else   { u0 = gp[cj]; u1 = gp[200 + cj]; u2 = gp[400 + cj]; }
      }
    }
    __syncthreads();
  }

  // drain: out[1023] on final h1 (parity 0)
  if (tid >= 800 && tid < 816) {
    const int o = (tid - 800) & 3, bb = (tid - 800) >> 2;
    const float* wf = sF + o*HDIM;
    const float* hv = sh + bb*HDIM;
    float s0 = 0.f, s1 = 0.f, s2 = 0.f, s3 = 0.f;
    #pragma unroll 10
    for (int k = 0; k < HDIM; k += 4) {
      float4 W = *(const float4*)(wf + k);
      float4 H = *(const float4*)(hv + k);
      s0 = fmaf(W.x, H.x, s0); s1 = fmaf(W.y, H.y, s1);
      s2 = fmaf(W.z, H.z, s2); s3 = fmaf(W.w, H.w, s3);
    }
    float v = tanh_f(s0 + s1 + s2 + s3 + sbf[o]);
    out[((size_t)(b0 + bb) * TSTEPS + (TSTEPS - 1)) * 4 + o] = v;
  }
}

// ============================ launch =======================================
extern "C" void kernel_launch(void* const* d_in, const int* in_sizes, int n_in,
                              void* d_out, int out_size) {
  (void)in_sizes; (void)n_in; (void)out_size;
  const float* x     = (const float*)d_in[0];
  const float* W_ih0 = (const float*)d_in[1];
  const float* W_hh0 = (const float*)d_in[2];
  const float* b_ih0 = (const float*)d_in[3];
  const float* b_hh0 = (const float*)d_in[4];
  const float* W_ih1 = (const float*)d_in[5];
  const float* W_hh1 = (const float*)d_in[6];
  const float* b_ih1 = (const float*)d_in[7];
  const float* b_hh1 = (const float*)d_in[8];
  const float* W_fc  = (const float*)d_in[9];
  const float* b_fc  = (const float*)d_in[10];

  k1_layer0<<<32, 832>>>(x, W_ih0, W_hh0, b_ih0, b_hh0);
  k2_gx1<<<512, 608>>>(W_ih1);
  k3_layer1<<<32, 832>>>(W_hh1, b_ih1, b_hh1, W_fc, b_fc, (float*)d_out);
}

// round 13
// speedup vs baseline: 3.4884x; 3.4884x over previous
#include <cuda_runtime.h>
#include <cstdint>
#include <cstddef>

// ---------------------------------------------------------------------------
// Layer-sequential 2-layer GRU. Recurrence kernels use 4-CTA clusters:
// each CTA holds 150 gate-rows of W_hh in SMEM (conflict-free layout:
// row stride 212 floats, quarter offset 52) and serves 4 batches.
// Thread (q, lrow) loads its 50-float weight quarter to regs once/step,
// FMA2s against 4 batches' h (warp-broadcast LDS). Quarter partials ->
// smem; cell threads (b, jl) finish gates and push h_new (200 x 4B) to all
// 4 CTAs via st.shared::cluster. ONE barrier.cluster per step.
//   K1: layer-0 recurrence, writes h0_post to g_h0.
//   K2: gx1 = W_ih1 . h0 (free-running GEMM, register quarter-rows).
//   K3: layer-1 recurrence (gx1 prefetched from gmem) + FC outputs.
// R12 fix: K3 dynamic smem size now covers O_B (was 36868 < O_B end 37264
// -> OOB smem writes -> illegal memory access).
// ---------------------------------------------------------------------------

#define TSTEPS 1024
#define HDIM   200
#define NBATCH 128
#define CLSZ   4
#define NB     4
#define NTHR   608

typedef unsigned long long u64;

__device__ float g_h0[(size_t)NBATCH * TSTEPS * HDIM];    // 105 MB
__device__ float g_gx1[(size_t)NBATCH * TSTEPS * 600];    // 315 MB

#define FMA2(acc_, a_, b_) \
  asm("fma.rn.f32x2 %0, %1, %2, %0;" : "+l"(acc_) : "l"(a_), "l"(b_))
#define UNPK2(lo_, hi_, v_) \
  asm("mov.b64 {%0,%1}, %2;" : "=f"(lo_), "=f"(hi_) : "l"(v_))

__device__ __forceinline__ void cluster_sync() {
  asm volatile("barrier.cluster.arrive.aligned;" ::: "memory");
  asm volatile("barrier.cluster.wait.aligned;" ::: "memory");
}
__device__ __forceinline__ float sigmoid_f(float x) {
  return __fdividef(1.0f, 1.0f + __expf(-x));
}
__device__ __forceinline__ float tanh_f(float x) {
  float e = __expf(-2.0f * x);
  return __fdividef(2.0f, 1.0f + e) - 1.0f;
}

// shared offsets (floats)
enum {
  O_W   = 0,          // [150 rows][212]  (quarter q at +q*52, 50 used)
  O_H   = 31800,      // [2][NB][208]     (quarter qh at +qh*52)
  O_DQ  = 33464,      // [4 q][150 rows][4 b]
  O_WI  = 35864,      // K1: [150][8] W_ih0 slice   (K3: O_F/O_BF live here)
  O_B   = 37064,      // [4][50] biases: rcomb, zcomb, nx, nh
  O_INB = 37264,      // [2][4][8]
  SM1_F = 37328
};
// K3 extras — placed inside K1's O_WI region (unused by K3); same total size.
enum {
  O_F   = 35864,      // [4][200] W_fc
  O_BF  = 36664,      // [4]
  SM3_F = SM1_F
};

extern __shared__ float smem[];

// ---- shared matvec core: 4-batch quarter dots -> O_DQ -------------------
__device__ __forceinline__ void matvec_quarters(int tid, int p) {
  const int qid = tid / 150, lrow = tid % 150;
  const float* wp = smem + O_W + lrow*212 + qid*52;
  u64 wreg[25];
  #pragma unroll
  for (int c = 0; c < 12; c++) {
    ulonglong2 W = *(const ulonglong2*)(wp + 4*c);
    wreg[2*c] = W.x; wreg[2*c + 1] = W.y;
  }
  wreg[24] = *(const u64*)(wp + 48);
  const float* hb = smem + O_H + p*(NB*208) + qid*52;
  u64 a0 = 0, a1 = 0, a2 = 0, a3 = 0;
  #pragma unroll
  for (int c = 0; c < 12; c++) {
    ulonglong2 H0 = *(const ulonglong2*)(hb + 0*208 + 4*c);
    ulonglong2 H1 = *(const ulonglong2*)(hb + 1*208 + 4*c);
    ulonglong2 H2 = *(const ulonglong2*)(hb + 2*208 + 4*c);
    ulonglong2 H3 = *(const ulonglong2*)(hb + 3*208 + 4*c);
    FMA2(a0, wreg[2*c], H0.x); FMA2(a0, wreg[2*c+1], H0.y);
    FMA2(a1, wreg[2*c], H1.x); FMA2(a1, wreg[2*c+1], H1.y);
    FMA2(a2, wreg[2*c], H2.x); FMA2(a2, wreg[2*c+1], H2.y);
    FMA2(a3, wreg[2*c], H3.x); FMA2(a3, wreg[2*c+1], H3.y);
  }
  FMA2(a0, wreg[24], *(const u64*)(hb + 0*208 + 48));
  FMA2(a1, wreg[24], *(const u64*)(hb + 1*208 + 48));
  FMA2(a2, wreg[24], *(const u64*)(hb + 2*208 + 48));
  FMA2(a3, wreg[24], *(const u64*)(hb + 3*208 + 48));
  float4 dv; float lo, hi;
  UNPK2(lo, hi, a0); dv.x = lo + hi;
  UNPK2(lo, hi, a1); dv.y = lo + hi;
  UNPK2(lo, hi, a2); dv.z = lo + hi;
  UNPK2(lo, hi, a3); dv.w = lo + hi;
  *(float4*)(smem + O_DQ + (qid*150 + lrow)*4) = dv;
}

__device__ __forceinline__ void load_whh_slice(int tid, const float* W, int rank) {
  for (int idx = tid; idx < 30000; idx += NTHR) {
    int lrow = idx / 200, kk = idx % 200;
    int qd = kk / 50, k = kk % 50;
    int g = lrow / 50, jl = lrow % 50;
    smem[O_W + lrow*212 + qd*52 + k] =
        W[(size_t)(g*200 + rank*50 + jl) * HDIM + kk];
  }
}

// ============================ K1: layer 0 ==================================
__global__ void __launch_bounds__(NTHR, 1) __cluster_dims__(CLSZ, 1, 1)
k1_layer0(const float* __restrict__ x,
          const float* __restrict__ W_ih0, const float* __restrict__ W_hh0,
          const float* __restrict__ b_ih0, const float* __restrict__ b_hh0)
{
  const int tid = threadIdx.x;
  uint32_t rank;
  asm("mov.u32 %0, %%cluster_ctarank;" : "=r"(rank));
  const int b0 = (blockIdx.x >> 2) * NB;
  uint32_t sb = (uint32_t)__cvta_generic_to_shared(smem);

  load_whh_slice(tid, W_hh0, (int)rank);
  for (int idx = tid; idx < 1200; idx += NTHR) {
    int lrow = idx >> 3, c = idx & 7;
    int g = lrow / 50, jl = lrow % 50;
    smem[O_WI + idx] = W_ih0[(size_t)(g*200 + (int)rank*50 + jl)*8 + c];
  }
  if (tid < 50) {
    int J = (int)rank*50 + tid;
    smem[O_B +       tid] = b_ih0[J]       + b_hh0[J];
    smem[O_B +  50 + tid] = b_ih0[200 + J] + b_hh0[200 + J];
    smem[O_B + 100 + tid] = b_ih0[400 + J];
    smem[O_B + 150 + tid] = b_hh0[400 + J];
  }
  for (int idx = tid; idx < 2*NB*208; idx += NTHR) smem[O_H + idx] = 0.f;
  if (tid < NB) {
    const float* xr = x + (size_t)(b0 + tid) * TSTEPS * 8;
    float4 em = *(const float4*)(xr + 4);
    float* i0 = smem + O_INB + tid*8;
    float* i1 = smem + O_INB + 32 + tid*8;
    i0[0] = 1.f; i0[1] = 1.f; i0[2] = 1.f; i0[3] = 1.f;
    i0[4] = em.x; i0[5] = em.y; i0[6] = em.z; i0[7] = em.w;
    i1[4] = em.x; i1[5] = em.y; i1[6] = em.z; i1[7] = em.w;
  }
  __syncthreads();
  cluster_sync();

  for (int t = 0; t < TSTEPS; t++) {
    const int p = t & 1, q = p ^ 1;

    if (tid < 600) {
      matvec_quarters(tid, p);
    } else if (tid < 600 + NB) {
      // stage inputs for step t+1 into INB[q]
      const int bb = tid - 600;
      float4 xv = *(const float4*)(x + ((size_t)(b0 + bb)*TSTEPS + t) * 8);
      float* ib = smem + O_INB + q*32 + bb*8;
      ib[0] = xv.x; ib[1] = xv.y; ib[2] = xv.z; ib[3] = xv.w;
    }
    __syncthreads();

    if (tid < 200) {
      const int cb = tid / 50, jl = tid % 50;
      float dr = 0.f, dz = 0.f, dn = 0.f;
      #pragma unroll
      for (int qd = 0; qd < 4; qd++) {
        dr += smem[O_DQ + (qd*150 +       jl)*4 + cb];
        dz += smem[O_DQ + (qd*150 +  50 + jl)*4 + cb];
        dn += smem[O_DQ + (qd*150 + 100 + jl)*4 + cb];
      }
      const float* ib = smem + O_INB + p*32 + cb*8;
      float xr = smem[O_B + jl], xz = smem[O_B + 50 + jl], xn = smem[O_B + 100 + jl];
      #pragma unroll
      for (int c = 0; c < 8; c++) {
        float ic = ib[c];
        xr = fmaf(smem[O_WI + (      jl)*8 + c], ic, xr);
        xz = fmaf(smem[O_WI + ( 50 + jl)*8 + c], ic, xz);
        xn = fmaf(smem[O_WI + (100 + jl)*8 + c], ic, xn);
      }
      float rr = sigmoid_f(xr + dr);
      float zz = sigmoid_f(xz + dz);
      float nn = tanh_f(xn + rr * (dn + smem[O_B + 150 + jl]));
      float ho = smem[O_H + p*(NB*208) + cb*208 + (int)rank*52 + jl];
      float hn = nn + zz * (ho - nn);
      uint32_t la = sb + (uint32_t)(O_H + q*(NB*208) + cb*208 + (int)rank*52 + jl) * 4;
      #pragma unroll
      for (int rr2 = 0; rr2 < CLSZ; rr2++) {
        uint32_t ra;
        asm("mapa.shared::cluster.u32 %0, %1, %2;" : "=r"(ra) : "r"(la), "r"(rr2));
        asm volatile("st.shared::cluster.f32 [%0], %1;" :: "r"(ra), "f"(hn) : "memory");
      }
      g_h0[((size_t)(b0 + cb)*TSTEPS + t)*HDIM + (int)rank*50 + jl] = hn;
    }
    cluster_sync();
  }
}

// ============================ K2: gx1 GEMM =================================
__global__ void __launch_bounds__(608, 1)
k2_gx1(const float* __restrict__ W_ih1)
{
  __shared__ __align__(16) float ht[8 * HDIM];

  const int tid = threadIdx.x;
  const int b  = blockIdx.x >> 2;
  const int rq = blockIdx.x & 3;
  const int row = tid >> 2, q4 = tid & 3;
  const int grow = rq*150 + row;
  const unsigned mask = (tid < 576) ? 0xffffffffu : 0x00ffffffu;

  u64 wreg[25];
  if (tid < 600) {
    const u64* src = (const u64*)(W_ih1 + (size_t)grow * HDIM + q4*50);
    #pragma unroll
    for (int c = 0; c < 25; c++) wreg[c] = src[c];
  }
  const float* hin = g_h0 + (size_t)b * TSTEPS * HDIM;
  float* gout = g_gx1 + (size_t)b * TSTEPS * 600;

  for (int tb = 0; tb < TSTEPS; tb += 8) {
    __syncthreads();
    if (tid < 400)
      ((float4*)ht)[tid] = ((const float4*)(hin + (size_t)tb * HDIM))[tid];
    __syncthreads();
    if (tid < 600) {
      #pragma unroll 2
      for (int tt = 0; tt < 8; tt++) {
        const u64* hq = (const u64*)(ht + tt*HDIM + q4*50);
        u64 acc = 0;
        #pragma unroll
        for (int c = 0; c < 25; c++) FMA2(acc, wreg[c], hq[c]);
        float lo, hi; UNPK2(lo, hi, acc);
        float d = lo + hi;
        d += __shfl_xor_sync(mask, d, 1);
        d += __shfl_xor_sync(mask, d, 2);
        if (q4 == 0) gout[(size_t)(tb + tt)*600 + grow] = d;
      }
    }
  }
}

// ============================ K3: layer 1 + FC =============================
__global__ void __launch_bounds__(NTHR, 1) __cluster_dims__(CLSZ, 1, 1)
k3_layer1(const float* __restrict__ W_hh1,
          const float* __restrict__ b_ih1, const float* __restrict__ b_hh1,
          const float* __restrict__ W_fc,  const float* __restrict__ b_fc,
          float* __restrict__ out)
{
  const int tid = threadIdx.x;
  uint32_t rank;
  asm("mov.u32 %0, %%cluster_ctarank;" : "=r"(rank));
  const int b0 = (blockIdx.x >> 2) * NB;
  uint32_t sb = (uint32_t)__cvta_generic_to_shared(smem);

  load_whh_slice(tid, W_hh1, (int)rank);
  if (tid < 50) {
    int J = (int)rank*50 + tid;
    smem[O_B +       tid] = b_ih1[J]       + b_hh1[J];
    smem[O_B +  50 + tid] = b_ih1[200 + J] + b_hh1[200 + J];
    smem[O_B + 100 + tid] = b_ih1[400 + J];
    smem[O_B + 150 + tid] = b_hh1[400 + J];
  }
  for (int idx = tid; idx < 800; idx += NTHR) smem[O_F + idx] = W_fc[idx];
  if (tid < 4) smem[O_BF + tid] = b_fc[tid];
  for (int idx = tid; idx < 2*NB*208; idx += NTHR) smem[O_H + idx] = 0.f;

  // gx1 prefetch ring for cell threads
  const int cb = (tid < 200) ? tid / 50 : 0;
  const int jl = tid % 50;
  const float* gin = g_gx1 + (size_t)(b0 + cb) * TSTEPS * 600;
  const int goff = (int)rank*50 + jl;
  float u0=0.f,u1=0.f,u2=0.f, v0=0.f,v1=0.f,v2=0.f;
  if (tid < 200) {
    u0 = gin[goff];        u1 = gin[200 + goff];  u2 = gin[400 + goff];
    v0 = gin[600 + goff];  v1 = gin[800 + goff];  v2 = gin[1000 + goff];
  }
  __syncthreads();
  cluster_sync();

  for (int t = 0; t < TSTEPS; t++) {
    const int p = t & 1, q = p ^ 1;

    if (tid < 600) {
      matvec_quarters(tid, p);
    } else if (tid < 604 && t > 0) {
      // FC: out[t-1] for batch b0+rank, output o
      const int o = tid - 600;
      const float* wf = smem + O_F + o*HDIM;
      const float* hv = smem + O_H + p*(NB*208) + (int)rank*208;
      float s = 0.f;
      #pragma unroll
      for (int qh = 0; qh < 4; qh++) {
        const float* h5 = hv + qh*52;
        const float* w5 = wf + qh*50;
        #pragma unroll 10
        for (int k = 0; k < 50; k++) s = fmaf(w5[k], h5[k], s);
      }
      out[((size_t)(b0 + (int)rank)*TSTEPS + (t - 1))*4 + o] =
          tanh_f(s + smem[O_BF + o]);
    }
    __syncthreads();

    if (tid < 200) {
      float dr = 0.f, dz = 0.f, dn = 0.f;
      #pragma unroll
      for (int qd = 0; qd < 4; qd++) {
        dr += smem[O_DQ + (qd*150 +       jl)*4 + cb];
        dz += smem[O_DQ + (qd*150 +  50 + jl)*4 + cb];
        dn += smem[O_DQ + (qd*150 + 100 + jl)*4 + cb];
      }
      float gr = p ? v0 : u0;
      float gz = p ? v1 : u1;
      float gn = p ? v2 : u2;
      float rr = sigmoid_f(gr + dr + smem[O_B + jl]);
      float zz = sigmoid_f(gz + dz + smem[O_B + 50 + jl]);
      float nn = tanh_f(gn + smem[O_B + 100 + jl] +
                        rr * (dn + smem[O_B + 150 + jl]));
      float ho = smem[O_H + p*(NB*208) + cb*208 + (int)rank*52 + jl];
      float hn = nn + zz * (ho - nn);
      uint32_t la = sb + (uint32_t)(O_H + q*(NB*208) + cb*208 + (int)rank*52 + jl) * 4;
      #pragma unroll
      for (int rr2 = 0; rr2 < CLSZ; rr2++) {
        uint32_t ra;
        asm("mapa.shared::cluster.u32 %0, %1, %2;" : "=r"(ra) : "r"(la), "r"(rr2));
        asm volatile("st.shared::cluster.f32 [%0], %1;" :: "r"(ra), "f"(hn) : "memory");
      }
      if (t + 2 < TSTEPS) {
        const float* gp = gin + (size_t)(t + 2)*600;
        if (p) { v0 = gp[goff]; v1 = gp[200 + goff]; v2 = gp[400 + goff]; }
        else   { u0 = gp[goff]; u1 = gp[200 + goff]; u2 = gp[400 + goff]; }
      }
    }
    cluster_sync();
  }

  // drain: out[1023] from final h1 (parity 0)
  if (tid >= 600 && tid < 604) {
    const int o = tid - 600;
    const float* wf = smem + O_F + o*HDIM;
    const float* hv = smem + O_H + (int)rank*208;
    float s = 0.f;
    #pragma unroll
    for (int qh = 0; qh < 4; qh++) {
      const float* h5 = hv + qh*52;
      const float* w5 = wf + qh*50;
      #pragma unroll 10
      for (int k = 0; k < 50; k++) s = fmaf(w5[k], h5[k], s);
    }
    out[((size_t)(b0 + (int)rank)*TSTEPS + (TSTEPS - 1))*4 + o] =
        tanh_f(s + smem[O_BF + o]);
  }
}

// ============================ launch =======================================
extern "C" void kernel_launch(void* const* d_in, const int* in_sizes, int n_in,
                              void* d_out, int out_size) {
  (void)in_sizes; (void)n_in; (void)out_size;
  const float* x     = (const float*)d_in[0];
  const float* W_ih0 = (const float*)d_in[1];
  const float* W_hh0 = (const float*)d_in[2];
  const float* b_ih0 = (const float*)d_in[3];
  const float* b_hh0 = (const float*)d_in[4];
  const float* W_ih1 = (const float*)d_in[5];
  const float* W_hh1 = (const float*)d_in[6];
  const float* b_ih1 = (const float*)d_in[7];
  const float* b_hh1 = (const float*)d_in[8];
  const float* W_fc  = (const float*)d_in[9];
  const float* b_fc  = (const float*)d_in[10];

  cudaFuncSetAttribute(k1_layer0,
                       cudaFuncAttributeMaxDynamicSharedMemorySize, SM1_F*4);
  cudaFuncSetAttribute(k3_layer1,
                       cudaFuncAttributeMaxDynamicSharedMemorySize, SM3_F*4);

  k1_layer0<<<128, NTHR, SM1_F*4>>>(x, W_ih0, W_hh0, b_ih0, b_hh0);
  k2_gx1<<<512, 608>>>(W_ih1);
  k3_layer1<<<128, NTHR, SM3_F*4>>>(W_hh1, b_ih1, b_hh1, W_fc, b_fc,
                                    (float*)d_out);
}

// round 16
// speedup vs baseline: 3.6339x; 1.0417x over previous
#include <cuda_runtime.h>
#include <cstdint>
#include <cstddef>

// ---------------------------------------------------------------------------
// Layer-sequential 2-layer GRU. R14 = R13 with K2's h-tile loads changed
// from ulonglong2 (16B, misaligned at q4*50 floats = 200 B) to u64 pairs
// (8B-aligned everywhere). K1/K3 unchanged from the passing R12 version.
// ---------------------------------------------------------------------------

#define TSTEPS 1024
#define HDIM   200
#define NBATCH 128
#define CLSZ   4
#define NB     4
#define NTHR   608

typedef unsigned long long u64;

__device__ float g_h0[(size_t)NBATCH * TSTEPS * HDIM];    // 105 MB
__device__ float g_gx1[(size_t)NBATCH * TSTEPS * 600];    // 315 MB

#define FMA2(acc_, a_, b_) \
  asm("fma.rn.f32x2 %0, %1, %2, %0;" : "+l"(acc_) : "l"(a_), "l"(b_))
#define UNPK2(lo_, hi_, v_) \
  asm("mov.b64 {%0,%1}, %2;" : "=f"(lo_), "=f"(hi_) : "l"(v_))

__device__ __forceinline__ void cluster_sync() {
  asm volatile("barrier.cluster.arrive.aligned;" ::: "memory");
  asm volatile("barrier.cluster.wait.aligned;" ::: "memory");
}
__device__ __forceinline__ float sigmoid_f(float x) {
  return __fdividef(1.0f, 1.0f + __expf(-x));
}
__device__ __forceinline__ float tanh_f(float x) {
  float e = __expf(-2.0f * x);
  return __fdividef(2.0f, 1.0f + e) - 1.0f;
}

// shared offsets (floats)
enum {
  O_W   = 0,          // [150 rows][212]  (quarter q at +q*52, 50 used)
  O_H   = 31800,      // [2][NB][208]     (quarter qh at +qh*52)
  O_DQ  = 33464,      // [4 q][150 rows][4 b]
  O_WI  = 35864,      // K1: [150][8] W_ih0 slice   (K3: O_F/O_BF live here)
  O_B   = 37064,      // [4][50] biases: rcomb, zcomb, nx, nh
  O_INB = 37264,      // [2][4][8]
  SM1_F = 37328
};
// K3 extras — placed inside K1's O_WI region (unused by K3); same total size.
enum {
  O_F   = 35864,      // [4][200] W_fc
  O_BF  = 36664,      // [4]
  SM3_F = SM1_F
};

extern __shared__ float smem[];

// ---- shared matvec core: 4-batch quarter dots -> O_DQ -------------------
__device__ __forceinline__ void matvec_quarters(int tid, int p) {
  const int qid = tid / 150, lrow = tid % 150;
  const float* wp = smem + O_W + lrow*212 + qid*52;
  u64 wreg[25];
  #pragma unroll
  for (int c = 0; c < 12; c++) {
    ulonglong2 W = *(const ulonglong2*)(wp + 4*c);
    wreg[2*c] = W.x; wreg[2*c + 1] = W.y;
  }
  wreg[24] = *(const u64*)(wp + 48);
  const float* hb = smem + O_H + p*(NB*208) + qid*52;
  u64 a0 = 0, a1 = 0, a2 = 0, a3 = 0;
  #pragma unroll
  for (int c = 0; c < 12; c++) {
    ulonglong2 H0 = *(const ulonglong2*)(hb + 0*208 + 4*c);
    ulonglong2 H1 = *(const ulonglong2*)(hb + 1*208 + 4*c);
    ulonglong2 H2 = *(const ulonglong2*)(hb + 2*208 + 4*c);
    ulonglong2 H3 = *(const ulonglong2*)(hb + 3*208 + 4*c);
    FMA2(a0, wreg[2*c], H0.x); FMA2(a0, wreg[2*c+1], H0.y);
    FMA2(a1, wreg[2*c], H1.x); FMA2(a1, wreg[2*c+1], H1.y);
    FMA2(a2, wreg[2*c], H2.x); FMA2(a2, wreg[2*c+1], H2.y);
    FMA2(a3, wreg[2*c], H3.x); FMA2(a3, wreg[2*c+1], H3.y);
  }
  FMA2(a0, wreg[24], *(const u64*)(hb + 0*208 + 48));
  FMA2(a1, wreg[24], *(const u64*)(hb + 1*208 + 48));
  FMA2(a2, wreg[24], *(const u64*)(hb + 2*208 + 48));
  FMA2(a3, wreg[24], *(const u64*)(hb + 3*208 + 48));
  float4 dv; float lo, hi;
  UNPK2(lo, hi, a0); dv.x = lo + hi;
  UNPK2(lo, hi, a1); dv.y = lo + hi;
  UNPK2(lo, hi, a2); dv.z = lo + hi;
  UNPK2(lo, hi, a3); dv.w = lo + hi;
  *(float4*)(smem + O_DQ + (qid*150 + lrow)*4) = dv;
}

__device__ __forceinline__ void load_whh_slice(int tid, const float* W, int rank) {
  for (int idx = tid; idx < 30000; idx += NTHR) {
    int lrow = idx / 200, kk = idx % 200;
    int qd = kk / 50, k = kk % 50;
    int g = lrow / 50, jl = lrow % 50;
    smem[O_W + lrow*212 + qd*52 + k] =
        W[(size_t)(g*200 + rank*50 + jl) * HDIM + kk];
  }
}

// ============================ K1: layer 0 ==================================
__global__ void __launch_bounds__(NTHR, 1) __cluster_dims__(CLSZ, 1, 1)
k1_layer0(const float* __restrict__ x,
          const float* __restrict__ W_ih0, const float* __restrict__ W_hh0,
          const float* __restrict__ b_ih0, const float* __restrict__ b_hh0)
{
  const int tid = threadIdx.x;
  uint32_t rank;
  asm("mov.u32 %0, %%cluster_ctarank;" : "=r"(rank));
  const int b0 = (blockIdx.x >> 2) * NB;
  uint32_t sb = (uint32_t)__cvta_generic_to_shared(smem);

  load_whh_slice(tid, W_hh0, (int)rank);
  for (int idx = tid; idx < 1200; idx += NTHR) {
    int lrow = idx >> 3, c = idx & 7;
    int g = lrow / 50, jl = lrow % 50;
    smem[O_WI + idx] = W_ih0[(size_t)(g*200 + (int)rank*50 + jl)*8 + c];
  }
  if (tid < 50) {
    int J = (int)rank*50 + tid;
    smem[O_B +       tid] = b_ih0[J]       + b_hh0[J];
    smem[O_B +  50 + tid] = b_ih0[200 + J] + b_hh0[200 + J];
    smem[O_B + 100 + tid] = b_ih0[400 + J];
    smem[O_B + 150 + tid] = b_hh0[400 + J];
  }
  for (int idx = tid; idx < 2*NB*208; idx += NTHR) smem[O_H + idx] = 0.f;
  if (tid < NB) {
    const float* xr = x + (size_t)(b0 + tid) * TSTEPS * 8;
    float4 em = *(const float4*)(xr + 4);
    float* i0 = smem + O_INB + tid*8;
    float* i1 = smem + O_INB + 32 + tid*8;
    i0[0] = 1.f; i0[1] = 1.f; i0[2] = 1.f; i0[3] = 1.f;
    i0[4] = em.x; i0[5] = em.y; i0[6] = em.z; i0[7] = em.w;
    i1[4] = em.x; i1[5] = em.y; i1[6] = em.z; i1[7] = em.w;
  }
  __syncthreads();
  cluster_sync();

  for (int t = 0; t < TSTEPS; t++) {
    const int p = t & 1, q = p ^ 1;

    if (tid < 600) {
      matvec_quarters(tid, p);
    } else if (tid < 600 + NB) {
      // stage inputs for step t+1 into INB[q]
      const int bb = tid - 600;
      float4 xv = *(const float4*)(x + ((size_t)(b0 + bb)*TSTEPS + t) * 8);
      float* ib = smem + O_INB + q*32 + bb*8;
      ib[0] = xv.x; ib[1] = xv.y; ib[2] = xv.z; ib[3] = xv.w;
    }
    __syncthreads();

    if (tid < 200) {
      const int cb = tid / 50, jl = tid % 50;
      float dr = 0.f, dz = 0.f, dn = 0.f;
      #pragma unroll
      for (int qd = 0; qd < 4; qd++) {
        dr += smem[O_DQ + (qd*150 +       jl)*4 + cb];
        dz += smem[O_DQ + (qd*150 +  50 + jl)*4 + cb];
        dn += smem[O_DQ + (qd*150 + 100 + jl)*4 + cb];
      }
      const float* ib = smem + O_INB + p*32 + cb*8;
      float xr = smem[O_B + jl], xz = smem[O_B + 50 + jl], xn = smem[O_B + 100 + jl];
      #pragma unroll
      for (int c = 0; c < 8; c++) {
        float ic = ib[c];
        xr = fmaf(smem[O_WI + (      jl)*8 + c], ic, xr);
        xz = fmaf(smem[O_WI + ( 50 + jl)*8 + c], ic, xz);
        xn = fmaf(smem[O_WI + (100 + jl)*8 + c], ic, xn);
      }
      float rr = sigmoid_f(xr + dr);
      float zz = sigmoid_f(xz + dz);
      float nn = tanh_f(xn + rr * (dn + smem[O_B + 150 + jl]));
      float ho = smem[O_H + p*(NB*208) + cb*208 + (int)rank*52 + jl];
      float hn = nn + zz * (ho - nn);
      uint32_t la = sb + (uint32_t)(O_H + q*(NB*208) + cb*208 + (int)rank*52 + jl) * 4;
      #pragma unroll
      for (int rr2 = 0; rr2 < CLSZ; rr2++) {
        uint32_t ra;
        asm("mapa.shared::cluster.u32 %0, %1, %2;" : "=r"(ra) : "r"(la), "r"(rr2));
        asm volatile("st.shared::cluster.f32 [%0], %1;" :: "r"(ra), "f"(hn) : "memory");
      }
      g_h0[((size_t)(b0 + cb)*TSTEPS + t)*HDIM + (int)rank*50 + jl] = hn;
    }
    cluster_sync();
  }
}

// ============================ K2: gx1 GEMM (v2, u64 loads) =================
// grid: b (128) x rq (4) x th (2).  CTA: 150 rows x 512 timesteps.
// Thread (row, q4): W_ih1 quarter-row in 25 u64 regs; h in 16-step smem
// tiles; 4 timesteps per pass with 4 independent accumulator chains.
// h reads are u64 (8B-aligned at q4*50 floats); NOT ulonglong2.
__global__ void __launch_bounds__(NTHR, 1)
k2_gx1(const float* __restrict__ W_ih1)
{
  __shared__ __align__(16) float ht[16 * HDIM];   // 12.8 KB

  const int tid = threadIdx.x;
  const int b  = blockIdx.x >> 3;
  const int rq = (blockIdx.x >> 1) & 3;
  const int th = blockIdx.x & 1;
  const int row = tid >> 2, q4 = tid & 3;
  const int grow = rq*150 + row;
  const unsigned mask = (tid < 576) ? 0xffffffffu : 0x00ffffffu;

  u64 wreg[25];
  if (tid < 600) {
    const u64* src = (const u64*)(W_ih1 + (size_t)grow * HDIM + q4*50);
    #pragma unroll
    for (int c = 0; c < 25; c++) wreg[c] = src[c];
  }
  const float* hin = g_h0 + ((size_t)b * TSTEPS + th*512) * HDIM;
  float* gout = g_gx1 + ((size_t)b * TSTEPS + th*512) * 600;

  for (int tb = 0; tb < 512; tb += 16) {
    __syncthreads();
    // load 16x200 h tile (3200 floats = 800 float4), coalesced
    for (int i = tid; i < 800; i += NTHR)
      ((float4*)ht)[i] = ((const float4*)(hin + (size_t)tb * HDIM))[i];
    __syncthreads();
    if (tid < 600) {
      #pragma unroll
      for (int tt = 0; tt < 16; tt += 4) {
        const u64* h0p = (const u64*)(ht + (tt + 0)*HDIM + q4*50);
        const u64* h1p = (const u64*)(ht + (tt + 1)*HDIM + q4*50);
        const u64* h2p = (const u64*)(ht + (tt + 2)*HDIM + q4*50);
        const u64* h3p = (const u64*)(ht + (tt + 3)*HDIM + q4*50);
        u64 a0 = 0, a1 = 0, a2 = 0, a3 = 0;
        #pragma unroll
        for (int c = 0; c < 25; c++) {
          FMA2(a0, wreg[c], h0p[c]);
          FMA2(a1, wreg[c], h1p[c]);
          FMA2(a2, wreg[c], h2p[c]);
          FMA2(a3, wreg[c], h3p[c]);
        }
        float d0, d1, d2, d3, lo, hi;
        UNPK2(lo, hi, a0); d0 = lo + hi;
        UNPK2(lo, hi, a1); d1 = lo + hi;
        UNPK2(lo, hi, a2); d2 = lo + hi;
        UNPK2(lo, hi, a3); d3 = lo + hi;
        d0 += __shfl_xor_sync(mask, d0, 1);
        d0 += __shfl_xor_sync(mask, d0, 2);
        d1 += __shfl_xor_sync(mask, d1, 1);
        d1 += __shfl_xor_sync(mask, d1, 2);
        d2 += __shfl_xor_sync(mask, d2, 1);
        d2 += __shfl_xor_sync(mask, d2, 2);
        d3 += __shfl_xor_sync(mask, d3, 1);
        d3 += __shfl_xor_sync(mask, d3, 2);
        if (q4 == 0) {
          gout[(size_t)(tb + tt + 0)*600 + grow] = d0;
          gout[(size_t)(tb + tt + 1)*600 + grow] = d1;
          gout[(size_t)(tb + tt + 2)*600 + grow] = d2;
          gout[(size_t)(tb + tt + 3)*600 + grow] = d3;
        }
      }
    }
  }
}

// ============================ K3: layer 1 + FC =============================
__global__ void __launch_bounds__(NTHR, 1) __cluster_dims__(CLSZ, 1, 1)
k3_layer1(const float* __restrict__ W_hh1,
          const float* __restrict__ b_ih1, const float* __restrict__ b_hh1,
          const float* __restrict__ W_fc,  const float* __restrict__ b_fc,
          float* __restrict__ out)
{
  const int tid = threadIdx.x;
  uint32_t rank;
  asm("mov.u32 %0, %%cluster_ctarank;" : "=r"(rank));
  const int b0 = (blockIdx.x >> 2) * NB;
  uint32_t sb = (uint32_t)__cvta_generic_to_shared(smem);

  load_whh_slice(tid, W_hh1, (int)rank);
  if (tid < 50) {
    int J = (int)rank*50 + tid;
    smem[O_B +       tid] = b_ih1[J]       + b_hh1[J];
    smem[O_B +  50 + tid] = b_ih1[200 + J] + b_hh1[200 + J];
    smem[O_B + 100 + tid] = b_ih1[400 + J];
    smem[O_B + 150 + tid] = b_hh1[400 + J];
  }
  for (int idx = tid; idx < 800; idx += NTHR) smem[O_F + idx] = W_fc[idx];
  if (tid < 4) smem[O_BF + tid] = b_fc[tid];
  for (int idx = tid; idx < 2*NB*208; idx += NTHR) smem[O_H + idx] = 0.f;

  // gx1 prefetch ring for cell threads
  const int cb = (tid < 200) ? tid / 50 : 0;
  const int jl = tid % 50;
  const float* gin = g_gx1 + (size_t)(b0 + cb) * TSTEPS * 600;
  const int goff = (int)rank*50 + jl;
  float u0=0.f,u1=0.f,u2=0.f, v0=0.f,v1=0.f,v2=0.f;
  if (tid < 200) {
    u0 = gin[goff];        u1 = gin[200 + goff];  u2 = gin[400 + goff];
    v0 = gin[600 + goff];  v1 = gin[800 + goff];  v2 = gin[1000 + goff];
  }
  __syncthreads();
  cluster_sync();

  for (int t = 0; t < TSTEPS; t++) {
    const int p = t & 1, q = p ^ 1;

    if (tid < 600) {
      matvec_quarters(tid, p);
    } else if (tid < 604 && t > 0) {
      // FC: out[t-1] for batch b0+rank, output o
      const int o = tid - 600;
      const float* wf = smem + O_F + o*HDIM;
      const float* hv = smem + O_H + p*(NB*208) + (int)rank*208;
      float s = 0.f;
      #pragma unroll
      for (int qh = 0; qh < 4; qh++) {
        const float* h5 = hv + qh*52;
        const float* w5 = wf + qh*50;
        #pragma unroll 10
        for (int k = 0; k < 50; k++) s = fmaf(w5[k], h5[k], s);
      }
      out[((size_t)(b0 + (int)rank)*TSTEPS + (t - 1))*4 + o] =
          tanh_f(s + smem[O_BF + o]);
    }
    __syncthreads();

    if (tid < 200) {
      float dr = 0.f, dz = 0.f, dn = 0.f;
      #pragma unroll
      for (int qd = 0; qd < 4; qd++) {
        dr += smem[O_DQ + (qd*150 +       jl)*4 + cb];
        dz += smem[O_DQ + (qd*150 +  50 + jl)*4 + cb];
        dn += smem[O_DQ + (qd*150 + 100 + jl)*4 + cb];
      }
      float gr = p ? v0 : u0;
      float gz = p ? v1 : u1;
      float gn = p ? v2 : u2;
      float rr = sigmoid_f(gr + dr + smem[O_B + jl]);
      float zz = sigmoid_f(gz + dz + smem[O_B + 50 + jl]);
      float nn = tanh_f(gn + smem[O_B + 100 + jl] +
                        rr * (dn + smem[O_B + 150 + jl]));
      float ho = smem[O_H + p*(NB*208) + cb*208 + (int)rank*52 + jl];
      float hn = nn + zz * (ho - nn);
      uint32_t la = sb + (uint32_t)(O_H + q*(NB*208) + cb*208 + (int)rank*52 + jl) * 4;
      #pragma unroll
      for (int rr2 = 0; rr2 < CLSZ; rr2++) {
        uint32_t ra;
        asm("mapa.shared::cluster.u32 %0, %1, %2;" : "=r"(ra) : "r"(la), "r"(rr2));
        asm volatile("st.shared::cluster.f32 [%0], %1;" :: "r"(ra), "f"(hn) : "memory");
      }
      if (t + 2 < TSTEPS) {
        const float* gp = gin + (size_t)(t + 2)*600;
        if (p) { v0 = gp[goff]; v1 = gp[200 + goff]; v2 = gp[400 + goff]; }
        else   { u0 = gp[goff]; u1 = gp[200 + goff]; u2 = gp[400 + goff]; }
      }
    }
    cluster_sync();
  }

  // drain: out[1023] from final h1 (parity 0)
  if (tid >= 600 && tid < 604) {
    const int o = tid - 600;
    const float* wf = smem + O_F + o*HDIM;
    const float* hv = smem + O_H + (int)rank*208;
    float s = 0.f;
    #pragma unroll
    for (int qh = 0; qh < 4; qh++) {
      const float* h5 = hv + qh*52;
      const float* w5 = wf + qh*50;
      #pragma unroll 10
      for (int k = 0; k < 50; k++) s = fmaf(w5[k], h5[k], s);
    }
    out[((size_t)(b0 + (int)rank)*TSTEPS + (TSTEPS - 1))*4 + o] =
        tanh_f(s + smem[O_BF + o]);
  }
}

// ============================ launch =======================================
extern "C" void kernel_launch(void* const* d_in, const int* in_sizes, int n_in,
                              void* d_out, int out_size) {
  (void)in_sizes; (void)n_in; (void)out_size;
  const float* x     = (const float*)d_in[0];
  const float* W_ih0 = (const float*)d_in[1];
  const float* W_hh0 = (const float*)d_in[2];
  const float* b_ih0 = (const float*)d_in[3];
  const float* b_hh0 = (const float*)d_in[4];
  const float* W_ih1 = (const float*)d_in[5];
  const float* W_hh1 = (const float*)d_in[6];
  const float* b_ih1 = (const float*)d_in[7];
  const float* b_hh1 = (const float*)d_in[8];
  const float* W_fc  = (const float*)d_in[9];
  const float* b_fc  = (const float*)d_in[10];

  cudaFuncSetAttribute(k1_layer0,
                       cudaFuncAttributeMaxDynamicSharedMemorySize, SM1_F*4);
  cudaFuncSetAttribute(k3_layer1,
                       cudaFuncAttributeMaxDynamicSharedMemorySize, SM3_F*4);

  k1_layer0<<<128, NTHR, SM1_F*4>>>(x, W_ih0, W_hh0, b_ih0, b_hh0);
  k2_gx1<<<1024, NTHR>>>(W_ih1);
  k3_layer1<<<128, NTHR, SM3_F*4>>>(W_hh1, b_ih1, b_hh1, W_fc, b_fc,
                                    (float*)d_out);
}